// round 16
// baseline (speedup 1.0000x reference)
#include <cuda_runtime.h>
#include <cstdint>

#define N_NODES 100000
#define N_EDGES 1000000
#define D 64
#define TILE_R 128
#define FSTRIDE 130
#define SAGE_SMEM_FLOATS (8192 + 2 * D * FSTRIDE)   // 24832 floats
#define SAGE_SMEM (SAGE_SMEM_FLOATS * 4)            // 99328 bytes
#define NB_SCAN ((N_NODES + 255) / 256)             // 391 scan blocks

// ---------------- scratch (device globals) -----------------------------------
__device__ float4 g_agg4[N_NODES * 16];   // neighbor feature MEANS
__device__ float4 g_h4[N_NODES * 16];     // layer-1 hidden output
__device__ int    g_row[N_NODES + 1];     // CSR row pointers (by dst)
__device__ int    g_cur[N_NODES];         // counts, then fill cursors
__device__ int    g_csr[N_EDGES];         // src ids grouped by dst
__device__ int    g_bsum[512];            // scan block sums

// ---------------- packed fp32x2 helpers (sm_10x) -----------------------------
__device__ __forceinline__ unsigned long long fma2(unsigned long long a,
                                                   unsigned long long b,
                                                   unsigned long long c) {
    unsigned long long d;
    asm("fma.rn.f32x2 %0, %1, %2, %3;" : "=l"(d) : "l"(a), "l"(b), "l"(c));
    return d;
}
__device__ __forceinline__ unsigned long long add2(unsigned long long a,
                                                   unsigned long long b) {
    unsigned long long d;
    asm("add.rn.f32x2 %0, %1, %2;" : "=l"(d) : "l"(a), "l"(b));
    return d;
}
__device__ __forceinline__ unsigned long long pack2(float lo, float hi) {
    unsigned long long d;
    asm("mov.b64 %0, {%1, %2};" : "=l"(d) : "f"(lo), "f"(hi));
    return d;
}
__device__ __forceinline__ void unpack2(unsigned long long v, float& lo, float& hi) {
    asm("mov.b64 {%0, %1}, %2;" : "=f"(lo), "=f"(hi) : "l"(v));
}

// ================= CSR build ==================================================
__global__ void k_cnt_zero() {
    int i = blockIdx.x * blockDim.x + threadIdx.x;
    if (i < N_NODES) g_cur[i] = 0;
}

__global__ void k_hist(const int* __restrict__ dst) {
    int e = blockIdx.x * blockDim.x + threadIdx.x;
    if (e < N_EDGES) atomicAdd(&g_cur[dst[e]], 1);
}

// per-block exclusive scan of counts -> g_row, block totals -> g_bsum
__global__ void k_scan_block() {
    __shared__ int sh[256];
    int t = threadIdx.x;
    int i = blockIdx.x * 256 + t;
    int c = (i < N_NODES) ? g_cur[i] : 0;
    sh[t] = c;
    __syncthreads();
    #pragma unroll
    for (int off = 1; off < 256; off <<= 1) {
        int v = (t >= off) ? sh[t - off] : 0;
        __syncthreads();
        sh[t] += v;
        __syncthreads();
    }
    if (i < N_NODES) g_row[i] = sh[t] - c;   // exclusive
    if (t == 255) g_bsum[blockIdx.x] = sh[t];
}

// single WARP: exclusive scan of the 391 block sums in place
#define SCAN_PER_LANE ((NB_SCAN + 31) / 32)   // 13
__global__ void k_scan_tops() {
    int lane = threadIdx.x;
    int base = lane * SCAN_PER_LANE;
    int v[SCAN_PER_LANE];
    int sum = 0;
    #pragma unroll
    for (int i = 0; i < SCAN_PER_LANE; i++) {
        int idx = base + i;
        v[i] = (idx < NB_SCAN) ? g_bsum[idx] : 0;
        sum += v[i];
    }
    int pre = sum;
    #pragma unroll
    for (int off = 1; off < 32; off <<= 1) {
        int o = __shfl_up_sync(0xffffffffu, pre, off);
        if (lane >= off) pre += o;
    }
    pre -= sum;
    #pragma unroll
    for (int i = 0; i < SCAN_PER_LANE; i++) {
        int idx = base + i;
        if (idx < NB_SCAN) g_bsum[idx] = pre;
        pre += v[i];
    }
}

// add block offsets; init cursors
__global__ void k_scan_add() {
    int i = blockIdx.x * blockDim.x + threadIdx.x;
    if (i < N_NODES) {
        int v = g_row[i] + g_bsum[i >> 8];
        g_row[i] = v;
        g_cur[i] = v;
    }
    if (i == 0) g_row[N_NODES] = N_EDGES;
}

__global__ void k_fill(const int* __restrict__ src, const int* __restrict__ dst) {
    int e = blockIdx.x * blockDim.x + threadIdx.x;
    if (e < N_EDGES) {
        int pos = atomicAdd(&g_cur[dst[e]], 1);
        g_csr[pos] = src[e];
    }
}

// ================= gather-mean: agg[n] = mean_{s in N(n)} feat[s] =============
// One warp per node; half-warp per edge parity; 2-way unroll -> 4 loads in flight.
template <bool FROM_H>
__global__ void __launch_bounds__(256)
k_gather(const float* __restrict__ xin) {
    int wid = (blockIdx.x * blockDim.x + threadIdx.x) >> 5;
    if (wid >= N_NODES) return;
    int lane = threadIdx.x & 31;
    int q = lane & 15;
    int h = lane >> 4;
    int beg = __ldg(&g_row[wid]);
    int end = __ldg(&g_row[wid + 1]);

    float4 a0 = make_float4(0.f, 0.f, 0.f, 0.f);
    float4 a1 = make_float4(0.f, 0.f, 0.f, 0.f);
    int e = beg + h;
    for (; e + 2 < end; e += 4) {
        int s0 = __ldg(&g_csr[e]);
        int s1 = __ldg(&g_csr[e + 2]);
        float4 v0, v1;
        if (FROM_H) { v0 = g_h4[s0 * 16 + q]; v1 = g_h4[s1 * 16 + q]; }
        else {
            v0 = __ldg((const float4*)xin + (long long)s0 * 16 + q);
            v1 = __ldg((const float4*)xin + (long long)s1 * 16 + q);
        }
        a0.x += v0.x; a0.y += v0.y; a0.z += v0.z; a0.w += v0.w;
        a1.x += v1.x; a1.y += v1.y; a1.z += v1.z; a1.w += v1.w;
    }
    if (e < end) {
        int s0 = __ldg(&g_csr[e]);
        float4 v0;
        if (FROM_H) v0 = g_h4[s0 * 16 + q];
        else        v0 = __ldg((const float4*)xin + (long long)s0 * 16 + q);
        a0.x += v0.x; a0.y += v0.y; a0.z += v0.z; a0.w += v0.w;
    }
    a0.x += a1.x; a0.y += a1.y; a0.z += a1.z; a0.w += a1.w;
    a0.x += __shfl_xor_sync(0xffffffffu, a0.x, 16);
    a0.y += __shfl_xor_sync(0xffffffffu, a0.y, 16);
    a0.z += __shfl_xor_sync(0xffffffffu, a0.z, 16);
    a0.w += __shfl_xor_sync(0xffffffffu, a0.w, 16);

    if (h == 0) {
        float inv = 1.0f / fmaxf((float)(end - beg), 1.0f);
        g_agg4[wid * 16 + q] = make_float4(a0.x * inv, a0.y * inv,
                                           a0.z * inv, a0.w * inv);
    }
}

// ================= fused SAGE layer (R6 core; unroll-4 pipelined) ==============
// out = selfX @ Wself + b + mean @ Wneigh (+ ReLU). Tile 128 rows x 64 cols.
// Block 256 = 8 warps; warp w: rows w*16..+15. Lanes 0-15 compute the Wself
// partial, lanes 16-31 the Wneigh partial; combined with shfl.xor(16).
template <bool RELU, bool IN_IS_H, bool OUT_IS_H>
__global__ void __launch_bounds__(256, 2)
k_sage(const float* __restrict__ xin,
       const float* __restrict__ Wself,
       const float* __restrict__ Wneigh,
       const float* __restrict__ bias,
       float* __restrict__ out) {
    extern __shared__ float smem[];
    float* sW  = smem;                    // [k*128 + quad*4 + j]: quads 0-15 Ws, 16-31 Wn
    float* sXk = smem + 8192;             // [k*FSTRIDE + row] (k-major)
    float* sMk = sXk + D * FSTRIDE;

    int tid  = threadIdx.x;
    int row0 = blockIdx.x * TILE_R;
    int lane = tid & 31;
    int j    = lane & 15;                 // output quad

    // hoist bias load: GMEM latency overlaps the staging phase
    float4 bq = __ldg((const float4*)bias + j);

    #pragma unroll
    for (int i = tid; i < 1024; i += 256) {
        int k = i >> 4, q = i & 15;
        ((float4*)sW)[k * 32 + q]      = __ldg((const float4*)Wself  + i);
        ((float4*)sW)[k * 32 + 16 + q] = __ldg((const float4*)Wneigh + i);
    }

    #pragma unroll
    for (int i = tid; i < TILE_R * 16; i += 256) {
        int r = i >> 4, q = i & 15;
        int grow = row0 + r;
        if (grow >= N_NODES) grow = N_NODES - 1;   // clamp; stores guarded
        float4 xv;
        if (IN_IS_H) xv = g_h4[grow * 16 + q];
        else         xv = __ldg((const float4*)xin + (long long)grow * 16 + q);
        float4 a = g_agg4[grow * 16 + q];          // already the mean
        int kb = q * 4;
        sXk[(kb + 0) * FSTRIDE + r] = xv.x;
        sXk[(kb + 1) * FSTRIDE + r] = xv.y;
        sXk[(kb + 2) * FSTRIDE + r] = xv.z;
        sXk[(kb + 3) * FSTRIDE + r] = xv.w;
        sMk[(kb + 0) * FSTRIDE + r] = a.x;
        sMk[(kb + 1) * FSTRIDE + r] = a.y;
        sMk[(kb + 2) * FSTRIDE + r] = a.z;
        sMk[(kb + 3) * FSTRIDE + r] = a.w;
    }
    __syncthreads();

    int w     = tid >> 5;
    int hf    = lane >> 4;                 // 0: x/Ws half, 1: m/Wn half
    int rbase = w * 16;                    // 16 rows per warp

    const float* feat = hf ? sMk : sXk;

    unsigned long long acc[8][4];
    {
        unsigned long long bi[4] = { pack2(bq.x, bq.x), pack2(bq.y, bq.y),
                                     pack2(bq.z, bq.z), pack2(bq.w, bq.w) };
        #pragma unroll
        for (int p = 0; p < 8; p++)
            #pragma unroll
            for (int c = 0; c < 4; c++)
                acc[p][c] = hf ? 0ULL : bi[c];
    }

    #pragma unroll 4
    for (int k = 0; k < D; k++) {
        float4 wq = ((const float4*)sW)[k * 32 + lane];
        unsigned long long w2[4] = { pack2(wq.x, wq.x), pack2(wq.y, wq.y),
                                     pack2(wq.z, wq.z), pack2(wq.w, wq.w) };
        const float* fk = &feat[k * FSTRIDE + rbase];
        unsigned long long f2[8];
        #pragma unroll
        for (int p = 0; p < 8; p++)
            f2[p] = *(const unsigned long long*)(fk + 2 * p);
        #pragma unroll
        for (int p = 0; p < 8; p++)
            #pragma unroll
            for (int c = 0; c < 4; c++)
                acc[p][c] = fma2(f2[p], w2[c], acc[p][c]);
    }

    #pragma unroll
    for (int p = 0; p < 8; p++)
        #pragma unroll
        for (int c = 0; c < 4; c++) {
            unsigned long long other =
                __shfl_xor_sync(0xffffffffu, acc[p][c], 16);
            acc[p][c] = add2(acc[p][c], other);
        }

    int pstart = hf * 4;
    #pragma unroll
    for (int p = pstart; p < pstart + 4; p++) {
        float l0, h0, l1, h1, l2, h2, l3, h3;
        unpack2(acc[p][0], l0, h0);
        unpack2(acc[p][1], l1, h1);
        unpack2(acc[p][2], l2, h2);
        unpack2(acc[p][3], l3, h3);
        if (RELU) {
            l0 = fmaxf(l0, 0.f); h0 = fmaxf(h0, 0.f);
            l1 = fmaxf(l1, 0.f); h1 = fmaxf(h1, 0.f);
            l2 = fmaxf(l2, 0.f); h2 = fmaxf(h2, 0.f);
            l3 = fmaxf(l3, 0.f); h3 = fmaxf(h3, 0.f);
        }
        float4 v0 = make_float4(l0, l1, l2, l3);   // row 2p
        float4 v1 = make_float4(h0, h1, h2, h3);   // row 2p+1
        int g0 = row0 + rbase + 2 * p;
        if (g0 < N_NODES) {
            if (OUT_IS_H) g_h4[g0 * 16 + j] = v0;
            else          *((float4*)out + (long long)g0 * 16 + j) = v0;
        }
        if (g0 + 1 < N_NODES) {
            if (OUT_IS_H) g_h4[(g0 + 1) * 16 + j] = v1;
            else          *((float4*)out + (long long)(g0 + 1) * 16 + j) = v1;
        }
    }
}

// ---------------- launcher ---------------------------------------------------
extern "C" void kernel_launch(void* const* d_in, const int* in_sizes, int n_in,
                              void* d_out, int out_size) {
    const float* x       = (const float*)d_in[0];
    const int*   src     = (const int*)d_in[1];
    const int*   dst     = (const int*)d_in[2];
    const float* Wself1  = (const float*)d_in[3];
    const float* Wneigh1 = (const float*)d_in[4];
    const float* b1      = (const float*)d_in[5];
    const float* Wself2  = (const float*)d_in[6];
    const float* Wneigh2 = (const float*)d_in[7];
    const float* b2      = (const float*)d_in[8];
    float* out = (float*)d_out;

    cudaFuncSetAttribute(k_sage<true, false, true>,
                         cudaFuncAttributeMaxDynamicSharedMemorySize, SAGE_SMEM);
    cudaFuncSetAttribute(k_sage<false, true, false>,
                         cudaFuncAttributeMaxDynamicSharedMemorySize, SAGE_SMEM);

    int ngrid = (N_NODES + 255) / 256;            // 391
    int egrid = (N_EDGES + 255) / 256;            // 3907
    int wgrid = (N_NODES * 32 + 255) / 256;       // 12500 (warp per node)
    int ggrid = (N_NODES + TILE_R - 1) / TILE_R;  // 782

    // CSR build (R6 validated pipeline)
    k_cnt_zero<<<ngrid, 256>>>();
    k_hist<<<egrid, 256>>>(dst);
    k_scan_block<<<NB_SCAN, 256>>>();
    k_scan_tops<<<1, 32>>>();
    k_scan_add<<<ngrid, 256>>>();
    k_fill<<<egrid, 256>>>(src, dst);

    // layer 1
    k_gather<false><<<wgrid, 256>>>(x);
    k_sage<true, false, true><<<ggrid, 256, SAGE_SMEM>>>(x, Wself1, Wneigh1, b1, nullptr);

    // layer 2
    k_gather<true><<<wgrid, 256>>>(nullptr);
    k_sage<false, true, false><<<ggrid, 256, SAGE_SMEM>>>(nullptr, Wself2, Wneigh2, b2, out);
}

// round 17
// speedup vs baseline: 1.0213x; 1.0213x over previous
#include <cuda_runtime.h>
#include <cstdint>

#define N_NODES 100000
#define N_EDGES 1000000
#define D 64
#define TILE_R 128
#define FSTRIDE 130
#define SAGE_SMEM_FLOATS (8192 + 2 * D * FSTRIDE)   // 24832 floats
#define SAGE_SMEM (SAGE_SMEM_FLOATS * 4)            // 99328 bytes
#define NB_SCAN ((N_NODES + 255) / 256)             // 391 scan blocks

// ---------------- scratch (device globals) -----------------------------------
__device__ float4 g_agg4[N_NODES * 16];   // neighbor feature MEANS
__device__ float4 g_h4[N_NODES * 16];     // layer-1 hidden output
__device__ int    g_row[N_NODES + 1];     // CSR row pointers (by dst)
__device__ int    g_cur[N_NODES];         // counts, then fill cursors
__device__ int    g_csr[N_EDGES];         // src ids grouped by dst
__device__ int    g_bsum[512];            // scan block sums

// ---------------- packed fp32x2 helpers (sm_10x) -----------------------------
__device__ __forceinline__ unsigned long long fma2(unsigned long long a,
                                                   unsigned long long b,
                                                   unsigned long long c) {
    unsigned long long d;
    asm("fma.rn.f32x2 %0, %1, %2, %3;" : "=l"(d) : "l"(a), "l"(b), "l"(c));
    return d;
}
__device__ __forceinline__ unsigned long long add2(unsigned long long a,
                                                   unsigned long long b) {
    unsigned long long d;
    asm("add.rn.f32x2 %0, %1, %2;" : "=l"(d) : "l"(a), "l"(b));
    return d;
}
__device__ __forceinline__ unsigned long long pack2(float lo, float hi) {
    unsigned long long d;
    asm("mov.b64 %0, {%1, %2};" : "=l"(d) : "f"(lo), "f"(hi));
    return d;
}
__device__ __forceinline__ void unpack2(unsigned long long v, float& lo, float& hi) {
    asm("mov.b64 {%0, %1}, %2;" : "=f"(lo), "=f"(hi) : "l"(v));
}

// ================= CSR build ==================================================
__global__ void k_cnt_zero() {
    int i = blockIdx.x * blockDim.x + threadIdx.x;
    if (i < N_NODES) g_cur[i] = 0;
}

__global__ void k_hist(const int* __restrict__ dst) {
    int e = blockIdx.x * blockDim.x + threadIdx.x;
    if (e < N_EDGES) atomicAdd(&g_cur[dst[e]], 1);
}

// per-block exclusive scan of counts -> g_row, block totals -> g_bsum
__global__ void k_scan_block() {
    __shared__ int sh[256];
    int t = threadIdx.x;
    int i = blockIdx.x * 256 + t;
    int c = (i < N_NODES) ? g_cur[i] : 0;
    sh[t] = c;
    __syncthreads();
    #pragma unroll
    for (int off = 1; off < 256; off <<= 1) {
        int v = (t >= off) ? sh[t - off] : 0;
        __syncthreads();
        sh[t] += v;
        __syncthreads();
    }
    if (i < N_NODES) g_row[i] = sh[t] - c;   // exclusive
    if (t == 255) g_bsum[blockIdx.x] = sh[t];
}

// single WARP: exclusive scan of the 391 block sums in place
#define SCAN_PER_LANE ((NB_SCAN + 31) / 32)   // 13
__global__ void k_scan_tops() {
    int lane = threadIdx.x;
    int base = lane * SCAN_PER_LANE;
    int v[SCAN_PER_LANE];
    int sum = 0;
    #pragma unroll
    for (int i = 0; i < SCAN_PER_LANE; i++) {
        int idx = base + i;
        v[i] = (idx < NB_SCAN) ? g_bsum[idx] : 0;
        sum += v[i];
    }
    int pre = sum;
    #pragma unroll
    for (int off = 1; off < 32; off <<= 1) {
        int o = __shfl_up_sync(0xffffffffu, pre, off);
        if (lane >= off) pre += o;
    }
    pre -= sum;
    #pragma unroll
    for (int i = 0; i < SCAN_PER_LANE; i++) {
        int idx = base + i;
        if (idx < NB_SCAN) g_bsum[idx] = pre;
        pre += v[i];
    }
}

// add block offsets; init cursors
__global__ void k_scan_add() {
    int i = blockIdx.x * blockDim.x + threadIdx.x;
    if (i < N_NODES) {
        int v = g_row[i] + g_bsum[i >> 8];
        g_row[i] = v;
        g_cur[i] = v;
    }
    if (i == 0) g_row[N_NODES] = N_EDGES;
}

__global__ void k_fill(const int* __restrict__ src, const int* __restrict__ dst) {
    int e = blockIdx.x * blockDim.x + threadIdx.x;
    if (e < N_EDGES) {
        int pos = atomicAdd(&g_cur[dst[e]], 1);
        g_csr[pos] = src[e];
    }
}

// ================= gather-mean: agg[n] = mean_{s in N(n)} feat[s] =============
// One warp per node; half-warp per edge parity; 2-way unroll -> 4 loads in flight.
template <bool FROM_H>
__global__ void __launch_bounds__(256)
k_gather(const float* __restrict__ xin) {
    int wid = (blockIdx.x * blockDim.x + threadIdx.x) >> 5;
    if (wid >= N_NODES) return;
    int lane = threadIdx.x & 31;
    int q = lane & 15;
    int h = lane >> 4;
    int beg = __ldg(&g_row[wid]);
    int end = __ldg(&g_row[wid + 1]);

    float4 a0 = make_float4(0.f, 0.f, 0.f, 0.f);
    float4 a1 = make_float4(0.f, 0.f, 0.f, 0.f);
    int e = beg + h;
    for (; e + 2 < end; e += 4) {
        int s0 = __ldg(&g_csr[e]);
        int s1 = __ldg(&g_csr[e + 2]);
        float4 v0, v1;
        if (FROM_H) { v0 = g_h4[s0 * 16 + q]; v1 = g_h4[s1 * 16 + q]; }
        else {
            v0 = __ldg((const float4*)xin + (long long)s0 * 16 + q);
            v1 = __ldg((const float4*)xin + (long long)s1 * 16 + q);
        }
        a0.x += v0.x; a0.y += v0.y; a0.z += v0.z; a0.w += v0.w;
        a1.x += v1.x; a1.y += v1.y; a1.z += v1.z; a1.w += v1.w;
    }
    if (e < end) {
        int s0 = __ldg(&g_csr[e]);
        float4 v0;
        if (FROM_H) v0 = g_h4[s0 * 16 + q];
        else        v0 = __ldg((const float4*)xin + (long long)s0 * 16 + q);
        a0.x += v0.x; a0.y += v0.y; a0.z += v0.z; a0.w += v0.w;
    }
    a0.x += a1.x; a0.y += a1.y; a0.z += a1.z; a0.w += a1.w;
    a0.x += __shfl_xor_sync(0xffffffffu, a0.x, 16);
    a0.y += __shfl_xor_sync(0xffffffffu, a0.y, 16);
    a0.z += __shfl_xor_sync(0xffffffffu, a0.z, 16);
    a0.w += __shfl_xor_sync(0xffffffffu, a0.w, 16);

    if (h == 0) {
        float inv = 1.0f / fmaxf((float)(end - beg), 1.0f);
        g_agg4[wid * 16 + q] = make_float4(a0.x * inv, a0.y * inv,
                                           a0.z * inv, a0.w * inv);
    }
}

// ================= fused SAGE layer (R6 validated optimum) =====================
// out = selfX @ Wself + b + mean @ Wneigh (+ ReLU). Tile 128 rows x 64 cols.
// Block 256 = 8 warps; warp w: rows w*16..+15. Lanes 0-15 compute the Wself
// partial, lanes 16-31 the Wneigh partial; combined with shfl.xor(16).
template <bool RELU, bool IN_IS_H, bool OUT_IS_H>
__global__ void __launch_bounds__(256, 2)
k_sage(const float* __restrict__ xin,
       const float* __restrict__ Wself,
       const float* __restrict__ Wneigh,
       const float* __restrict__ bias,
       float* __restrict__ out) {
    extern __shared__ float smem[];
    float* sW  = smem;                    // [k*128 + quad*4 + j]: quads 0-15 Ws, 16-31 Wn
    float* sXk = smem + 8192;             // [k*FSTRIDE + row] (k-major)
    float* sMk = sXk + D * FSTRIDE;

    int tid  = threadIdx.x;
    int row0 = blockIdx.x * TILE_R;

    #pragma unroll
    for (int i = tid; i < 1024; i += 256) {
        int k = i >> 4, q = i & 15;
        ((float4*)sW)[k * 32 + q]      = __ldg((const float4*)Wself  + i);
        ((float4*)sW)[k * 32 + 16 + q] = __ldg((const float4*)Wneigh + i);
    }

    #pragma unroll
    for (int i = tid; i < TILE_R * 16; i += 256) {
        int r = i >> 4, q = i & 15;
        int grow = row0 + r;
        if (grow >= N_NODES) grow = N_NODES - 1;   // clamp; stores guarded
        float4 xv;
        if (IN_IS_H) xv = g_h4[grow * 16 + q];
        else         xv = __ldg((const float4*)xin + (long long)grow * 16 + q);
        float4 a = g_agg4[grow * 16 + q];          // already the mean
        int kb = q * 4;
        sXk[(kb + 0) * FSTRIDE + r] = xv.x;
        sXk[(kb + 1) * FSTRIDE + r] = xv.y;
        sXk[(kb + 2) * FSTRIDE + r] = xv.z;
        sXk[(kb + 3) * FSTRIDE + r] = xv.w;
        sMk[(kb + 0) * FSTRIDE + r] = a.x;
        sMk[(kb + 1) * FSTRIDE + r] = a.y;
        sMk[(kb + 2) * FSTRIDE + r] = a.z;
        sMk[(kb + 3) * FSTRIDE + r] = a.w;
    }
    __syncthreads();

    int w     = tid >> 5;
    int lane  = tid & 31;
    int hf    = lane >> 4;                 // 0: x/Ws half, 1: m/Wn half
    int j     = lane & 15;                 // output quad
    int rbase = w * 16;                    // 16 rows per warp

    const float* feat = hf ? sMk : sXk;

    unsigned long long acc[8][4];
    {
        float b0 = __ldg(bias + 4 * j + 0);
        float b1 = __ldg(bias + 4 * j + 1);
        float b2 = __ldg(bias + 4 * j + 2);
        float b3 = __ldg(bias + 4 * j + 3);
        unsigned long long bi[4] = { pack2(b0, b0), pack2(b1, b1),
                                     pack2(b2, b2), pack2(b3, b3) };
        #pragma unroll
        for (int p = 0; p < 8; p++)
            #pragma unroll
            for (int c = 0; c < 4; c++)
                acc[p][c] = hf ? 0ULL : bi[c];
    }

    #pragma unroll 2
    for (int k = 0; k < D; k++) {
        float4 wq = ((const float4*)sW)[k * 32 + lane];
        unsigned long long w2[4] = { pack2(wq.x, wq.x), pack2(wq.y, wq.y),
                                     pack2(wq.z, wq.z), pack2(wq.w, wq.w) };
        const float* fk = &feat[k * FSTRIDE + rbase];
        unsigned long long f2[8];
        #pragma unroll
        for (int p = 0; p < 8; p++)
            f2[p] = *(const unsigned long long*)(fk + 2 * p);
        #pragma unroll
        for (int p = 0; p < 8; p++)
            #pragma unroll
            for (int c = 0; c < 4; c++)
                acc[p][c] = fma2(f2[p], w2[c], acc[p][c]);
    }

    #pragma unroll
    for (int p = 0; p < 8; p++)
        #pragma unroll
        for (int c = 0; c < 4; c++) {
            unsigned long long other =
                __shfl_xor_sync(0xffffffffu, acc[p][c], 16);
            acc[p][c] = add2(acc[p][c], other);
        }

    int pstart = hf * 4;
    #pragma unroll
    for (int p = pstart; p < pstart + 4; p++) {
        float l0, h0, l1, h1, l2, h2, l3, h3;
        unpack2(acc[p][0], l0, h0);
        unpack2(acc[p][1], l1, h1);
        unpack2(acc[p][2], l2, h2);
        unpack2(acc[p][3], l3, h3);
        if (RELU) {
            l0 = fmaxf(l0, 0.f); h0 = fmaxf(h0, 0.f);
            l1 = fmaxf(l1, 0.f); h1 = fmaxf(h1, 0.f);
            l2 = fmaxf(l2, 0.f); h2 = fmaxf(h2, 0.f);
            l3 = fmaxf(l3, 0.f); h3 = fmaxf(h3, 0.f);
        }
        float4 v0 = make_float4(l0, l1, l2, l3);   // row 2p
        float4 v1 = make_float4(h0, h1, h2, h3);   // row 2p+1
        int g0 = row0 + rbase + 2 * p;
        if (g0 < N_NODES) {
            if (OUT_IS_H) g_h4[g0 * 16 + j] = v0;
            else          *((float4*)out + (long long)g0 * 16 + j) = v0;
        }
        if (g0 + 1 < N_NODES) {
            if (OUT_IS_H) g_h4[(g0 + 1) * 16 + j] = v1;
            else          *((float4*)out + (long long)(g0 + 1) * 16 + j) = v1;
        }
    }
}

// ---------------- launcher ---------------------------------------------------
extern "C" void kernel_launch(void* const* d_in, const int* in_sizes, int n_in,
                              void* d_out, int out_size) {
    const float* x       = (const float*)d_in[0];
    const int*   src     = (const int*)d_in[1];
    const int*   dst     = (const int*)d_in[2];
    const float* Wself1  = (const float*)d_in[3];
    const float* Wneigh1 = (const float*)d_in[4];
    const float* b1      = (const float*)d_in[5];
    const float* Wself2  = (const float*)d_in[6];
    const float* Wneigh2 = (const float*)d_in[7];
    const float* b2      = (const float*)d_in[8];
    float* out = (float*)d_out;

    cudaFuncSetAttribute(k_sage<true, false, true>,
                         cudaFuncAttributeMaxDynamicSharedMemorySize, SAGE_SMEM);
    cudaFuncSetAttribute(k_sage<false, true, false>,
                         cudaFuncAttributeMaxDynamicSharedMemorySize, SAGE_SMEM);

    int ngrid = (N_NODES + 255) / 256;            // 391
    int egrid = (N_EDGES + 255) / 256;            // 3907
    int wgrid = (N_NODES * 32 + 255) / 256;       // 12500 (warp per node)
    int ggrid = (N_NODES + TILE_R - 1) / TILE_R;  // 782

    // CSR build (R6 validated pipeline)
    k_cnt_zero<<<ngrid, 256>>>();
    k_hist<<<egrid, 256>>>(dst);
    k_scan_block<<<NB_SCAN, 256>>>();
    k_scan_tops<<<1, 32>>>();
    k_scan_add<<<ngrid, 256>>>();
    k_fill<<<egrid, 256>>>(src, dst);

    // layer 1
    k_gather<false><<<wgrid, 256>>>(x);
    k_sage<true, false, true><<<ggrid, 256, SAGE_SMEM>>>(x, Wself1, Wneigh1, b1, nullptr);

    // layer 2
    k_gather<true><<<wgrid, 256>>>(nullptr);
    k_sage<false, true, false><<<ggrid, 256, SAGE_SMEM>>>(nullptr, Wself2, Wneigh2, b2, out);
}